// round 16
// baseline (speedup 1.0000x reference)
#include <cuda_runtime.h>
#include <cuda_bf16.h>
#include <cmath>

// BilinearInterpolation (spatial transformer grid sample)
// X: [B, C, H, W] fp32, theta: [B, 6] fp32 -> out: [B, C, H_OUT, W_OUT] fp32
//
// R15 = R14 (per-batch shear mapping) with the shear path's store-bounce
// rescheduled: channels processed in groups of 8 (8x4 independent LDGs in
// flight), then ONE barrier + 8 STS + ONE barrier + 8 coalesced stores.
// Barriers per block: 64 -> 16. Mapping, cost model, arithmetic chain all
// identical to R14/R13: rel_err must stay exactly 9.128e-4.

namespace {
constexpr int B = 16, C = 64, H = 256, W = 256;
constexpr int H_OUT = 256, W_OUT = 256;
constexpr int HW  = H * W;           // channel stride in X
constexpr int HWO = H_OUT * W_OUT;   // channel stride in out
constexpr int NBX = W_OUT / 16;      // 16
constexpr int NBY = H_OUT / 16;      // 16
constexpr int SLICE = 16 * 17;       // bounce slice (272 floats)
}

__global__ __launch_bounds__(256, 6)
void bilerp_kernel(const float* __restrict__ X,
                   const float* __restrict__ theta,
                   float* __restrict__ out) {
    __shared__ float bounce[8 * SLICE];   // 8 channel slices, 8.7KB

    // Block decode: blockIdx.x = b*256 + by*16 + bx  (16x16 pixel tile)
    const int bx = blockIdx.x & (NBX - 1);
    const int by = (blockIdx.x >> 4) & (NBY - 1);
    const int b  = blockIdx.x >> 8;

    const int lane = threadIdx.x & 31;
    const int w    = threadIdx.x >> 5;      // 0..7

    const float* th = theta + b * 6;
    const float t00 = __ldg(th + 0), t01 = __ldg(th + 1), t02 = __ldg(th + 2);
    const float t10 = __ldg(th + 3), t11 = __ldg(th + 4), t12 = __ldg(th + 5);

    const float ax0 = fabsf(t00), ax1 = fabsf(t01);
    const float ay0 = fabsf(t10), ay1 = fabsf(t11);

    // ---- axis shapes cost (R13) ----
    int   sx_best = 3;
    float c_best  = 3.0e38f;
    #pragma unroll
    for (int s = 4; s >= 1; --s) {
        const float wxf = (float)(1 << s);
        const float wyf = (float)(32 >> s);
        const float rows = wxf * ay0 + wyf * ay1 + 1.0f;
        const float cols = wxf * ax0 + wyf * ax1 + 2.0f;
        const float cost = 2.3f * rows * (1.0f + cols * 0.03125f) + wyf;
        if (cost < c_best) { c_best = cost; sx_best = s; }
    }

    // ---- shear option cost ----
    const float shear = (ay1 > 1.0e-6f) ? (-t10 / t11) : 1.0e9f;
    const bool  shear_ok = (fabsf(shear) <= 8.0f);
    float cost_sh = 3.0e38f;
    if (shear_ok) {
        const float rows_sh = 2.0f * ay1 + 2.0f;
        const float cols_sh = 15.0f * fabsf(t00 + t01 * shear) + ax1 + 2.0f;
        cost_sh = 2.3f * rows_sh * (1.0f + cols_sh * 0.03125f) + 4.0f;
    }
    const bool use_shear = shear_ok && (cost_sh < c_best);   // block-uniform

    // ---- thread -> pixel mapping ----
    int ix, iy, u = 0, v = 0, iyl = 0;
    if (use_shear) {
        u   = threadIdx.x & 15;
        v   = threadIdx.x >> 4;
        const int f = __float2int_rn(shear * (float)u);
        iyl = (v + f) & 15;
        ix  = bx * 16 + u;
        iy  = by * 16 + iyl;
    } else {
        const int sx  = sx_best;
        const int lx  = lane & ((1 << sx) - 1);
        const int ly  = lane >> sx;
        const int wox = (w & ((1 << (4 - sx)) - 1)) << sx;
        const int woy = (w >> (4 - sx)) << (5 - sx);
        ix = bx * 16 + wox + lx;
        iy = by * 16 + woy + ly;
    }

    // ---- identical arithmetic chain (R2..R14) ----
    const float xc = fmaf((float)ix, 2.0f / (float)(W_OUT - 1), -1.0f);
    const float yc = fmaf((float)iy, 2.0f / (float)(H_OUT - 1), -1.0f);

    const float xs = t00 * xc + t01 * yc + t02;
    const float ys = t10 * xc + t11 * yc + t12;

    const float x = (xs + 1.0f) * ((float)W * 0.5f);
    const float y = (ys + 1.0f) * ((float)H * 0.5f);

    int x0 = (int)floorf(x);
    int x1 = x0 + 1;
    int y0 = (int)floorf(y);
    int y1 = y0 + 1;
    x0 = min(max(x0, 0), W - 1);
    x1 = min(max(x1, 0), W - 1);
    y0 = min(max(y0, 0), H - 1);
    y1 = min(max(y1, 0), H - 1);

    const float x0f = (float)x0, x1f = (float)x1;
    const float y0f = (float)y0, y1f = (float)y1;

    const float wa = (x1f - x) * (y1f - y);
    const float wb = (x1f - x) * (y - y0f);
    const float wc = (x - x0f) * (y1f - y);
    const float wd = (x - x0f) * (y - y0f);

    const int oa = y0 * W + x0;   // == oc when x0==x1 ; == ob when y0==y1
    const int ob = y1 * W + x0;
    const int oc = y0 * W + x1;
    const int od = y1 * W + x1;

    const float* __restrict__ xp = X + (size_t)b * C * HW;

    const unsigned full = 0xFFFFFFFFu;
    const bool allx = __all_sync(full, x0 == x1);
    const bool ally = __all_sync(full, y0 == y1);

    if (use_shear) {
        // 8-channel groups: 32 independent LDGs, then 2 barriers per group.
        float* __restrict__ op =
            out + (size_t)b * C * HWO + (size_t)(by * 16 + v) * W_OUT + bx * 16 + u;
        const int sw = iyl * 17 + u;     // sheared write slot
        const int sr = v   * 17 + u;     // row-major read slot

        for (int g = 0; g < C; g += 8) {
            float vals[8];
            #pragma unroll
            for (int k = 0; k < 8; ++k) {
                const float* p = xp + (size_t)(g + k) * HW;
                const float pa = __ldg(p + oa);
                const float pb = ally ? pa : __ldg(p + ob);
                const float pc = allx ? pa : __ldg(p + oc);
                const float pd = allx ? pb : (ally ? pc : __ldg(p + od));
                vals[k] = wa * pa + wb * pb + wc * pc + wd * pd;
            }
            __syncthreads();             // previous group's bounce reads done
            #pragma unroll
            for (int k = 0; k < 8; ++k)
                bounce[k * SLICE + sw] = vals[k];
            __syncthreads();             // all writes visible
            #pragma unroll
            for (int k = 0; k < 8; ++k)
                op[(size_t)(g + k) * HWO] = bounce[k * SLICE + sr];
        }
    } else {
        float* __restrict__ op =
            out + (size_t)b * C * HWO + (size_t)iy * W_OUT + ix;

        if (allx & ally) {
            #pragma unroll 8
            for (int c = 0; c < C; ++c) {
                const float* p = xp + (size_t)c * HW;
                const float pa = __ldg(p + oa);
                op[(size_t)c * HWO] = wa * pa + wb * pa + wc * pa + wd * pa;
            }
        } else if (allx) {
            #pragma unroll 8
            for (int c = 0; c < C; ++c) {
                const float* p = xp + (size_t)c * HW;
                const float pa = __ldg(p + oa);
                const float pb = __ldg(p + ob);
                op[(size_t)c * HWO] = wa * pa + wb * pb + wc * pa + wd * pb;
            }
        } else if (ally) {
            #pragma unroll 8
            for (int c = 0; c < C; ++c) {
                const float* p = xp + (size_t)c * HW;
                const float pa = __ldg(p + oa);
                const float pc = __ldg(p + oc);
                op[(size_t)c * HWO] = wa * pa + wb * pa + wc * pc + wd * pc;
            }
        } else {
            #pragma unroll 8
            for (int c = 0; c < C; ++c) {
                const float* p = xp + (size_t)c * HW;
                const float pa = __ldg(p + oa);
                const float pb = __ldg(p + ob);
                const float pc = __ldg(p + oc);
                const float pd = __ldg(p + od);
                op[(size_t)c * HWO] = wa * pa + wb * pb + wc * pc + wd * pd;
            }
        }
    }
}

extern "C" void kernel_launch(void* const* d_in, const int* in_sizes, int n_in,
                              void* d_out, int out_size) {
    const float* X     = (const float*)d_in[0];
    const float* theta = (const float*)d_in[1];
    if (n_in >= 2 && in_sizes[0] == B * 6) {
        theta = (const float*)d_in[0];
        X     = (const float*)d_in[1];
    }
    float* out = (float*)d_out;

    dim3 grid(B * NBY * NBX);   // 4096 blocks (16x16 tiles)
    dim3 block(256);
    bilerp_kernel<<<grid, block>>>(X, theta, out);
}

// round 17
// speedup vs baseline: 1.1739x; 1.1739x over previous
#include <cuda_runtime.h>
#include <cuda_bf16.h>

// BilinearInterpolation (spatial transformer grid sample)
// X: [B, C, H, W] fp32, theta: [B, 6] fp32 -> out: [B, C, H_OUT, W_OUT] fp32
//
// R16 = R13 (adaptive axis warp shapes, best: 155.7us) with ONE change:
// __launch_bounds__(256, 8) caps registers at 32 (R4 proved the arithmetic
// fits), lifting occupancy 66% -> ~88% to saturate the L1tex pipe that
// binds this kernel (85.5% busy with stall bubbles at occ 66%).
// Mapping, cost model, arithmetic identical to R13:
// rel_err must stay exactly 9.128e-4.

namespace {
constexpr int B = 16, C = 64, H = 256, W = 256;
constexpr int H_OUT = 256, W_OUT = 256;
constexpr int HW  = H * W;           // channel stride in X
constexpr int HWO = H_OUT * W_OUT;   // channel stride in out
constexpr int NBX = W_OUT / 16;      // 16
constexpr int NBY = H_OUT / 16;      // 16
}

__global__ __launch_bounds__(256, 8)
void bilerp_kernel(const float* __restrict__ X,
                   const float* __restrict__ theta,
                   float* __restrict__ out) {
    // Block decode: blockIdx.x = b*256 + by*16 + bx  (16x16 pixel tile)
    const int bx = blockIdx.x & (NBX - 1);
    const int by = (blockIdx.x >> 4) & (NBY - 1);
    const int b  = blockIdx.x >> 8;

    const int lane = threadIdx.x & 31;
    const int w    = threadIdx.x >> 5;      // 0..7

    const float* th = theta + b * 6;
    const float t00 = __ldg(th + 0), t01 = __ldg(th + 1), t02 = __ldg(th + 2);
    const float t10 = __ldg(th + 3), t11 = __ldg(th + 4), t12 = __ldg(th + 5);

    // ---- adaptive warp shape: wx = 1<<sx, wy = 32>>sx, sx in {4,3,2,1} ----
    const float ax0 = fabsf(t00), ax1 = fabsf(t01);
    const float ay0 = fabsf(t10), ay1 = fabsf(t11);
    int   sx_best = 3;
    float c_best  = 3.0e38f;
    #pragma unroll
    for (int s = 4; s >= 1; --s) {
        const float wxf = (float)(1 << s);
        const float wyf = (float)(32 >> s);
        const float rows = wxf * ay0 + wyf * ay1 + 1.0f;
        const float cols = wxf * ax0 + wyf * ax1 + 2.0f;
        const float cost = 2.3f * rows * (1.0f + cols * 0.03125f) + wyf;
        if (cost < c_best) { c_best = cost; sx_best = s; }
    }
    const int sx  = sx_best;                // uniform across block (per batch)
    const int lx  = lane & ((1 << sx) - 1);
    const int ly  = lane >> sx;
    const int wox = (w & ((1 << (4 - sx)) - 1)) << sx;
    const int woy = (w >> (4 - sx)) << (5 - sx);

    const int ix = bx * 16 + wox + lx;
    const int iy = by * 16 + woy + ly;

    // ---- identical arithmetic chain (R2..R13) ----
    const float xc = fmaf((float)ix, 2.0f / (float)(W_OUT - 1), -1.0f);
    const float yc = fmaf((float)iy, 2.0f / (float)(H_OUT - 1), -1.0f);

    const float xs = t00 * xc + t01 * yc + t02;
    const float ys = t10 * xc + t11 * yc + t12;

    const float x = (xs + 1.0f) * ((float)W * 0.5f);
    const float y = (ys + 1.0f) * ((float)H * 0.5f);

    int x0 = (int)floorf(x);
    int x1 = x0 + 1;
    int y0 = (int)floorf(y);
    int y1 = y0 + 1;
    x0 = min(max(x0, 0), W - 1);
    x1 = min(max(x1, 0), W - 1);
    y0 = min(max(y0, 0), H - 1);
    y1 = min(max(y1, 0), H - 1);

    const float x0f = (float)x0, x1f = (float)x1;
    const float y0f = (float)y0, y1f = (float)y1;

    const float wa = (x1f - x) * (y1f - y);
    const float wb = (x1f - x) * (y - y0f);
    const float wc = (x - x0f) * (y1f - y);
    const float wd = (x - x0f) * (y - y0f);

    const int oa = y0 * W + x0;   // == oc when x0==x1 ; == ob when y0==y1
    const int ob = y1 * W + x0;
    const int oc = y0 * W + x1;
    const int od = y1 * W + x1;

    const float* __restrict__ xp = X + (size_t)b * C * HW;
    float* __restrict__ op = out + (size_t)b * C * HWO + (size_t)iy * W_OUT + ix;

    const unsigned full = 0xFFFFFFFFu;
    const bool allx = __all_sync(full, x0 == x1);
    const bool ally = __all_sync(full, y0 == y1);

    if (allx & ally) {
        // oa==ob==oc==od: one load feeds all four corners (bit-identical)
        #pragma unroll 8
        for (int c = 0; c < C; ++c) {
            const float* p = xp + (size_t)c * HW;
            const float pa = __ldg(p + oa);
            op[(size_t)c * HWO] = wa * pa + wb * pa + wc * pa + wd * pa;
        }
    } else if (allx) {
        // oc==oa, od==ob
        #pragma unroll 8
        for (int c = 0; c < C; ++c) {
            const float* p = xp + (size_t)c * HW;
            const float pa = __ldg(p + oa);
            const float pb = __ldg(p + ob);
            op[(size_t)c * HWO] = wa * pa + wb * pb + wc * pa + wd * pb;
        }
    } else if (ally) {
        // ob==oa, od==oc
        #pragma unroll 8
        for (int c = 0; c < C; ++c) {
            const float* p = xp + (size_t)c * HW;
            const float pa = __ldg(p + oa);
            const float pc = __ldg(p + oc);
            op[(size_t)c * HWO] = wa * pa + wb * pa + wc * pc + wd * pc;
        }
    } else {
        #pragma unroll 8
        for (int c = 0; c < C; ++c) {
            const float* p = xp + (size_t)c * HW;
            const float pa = __ldg(p + oa);
            const float pb = __ldg(p + ob);
            const float pc = __ldg(p + oc);
            const float pd = __ldg(p + od);
            op[(size_t)c * HWO] = wa * pa + wb * pb + wc * pc + wd * pd;
        }
    }
}

extern "C" void kernel_launch(void* const* d_in, const int* in_sizes, int n_in,
                              void* d_out, int out_size) {
    const float* X     = (const float*)d_in[0];
    const float* theta = (const float*)d_in[1];
    if (n_in >= 2 && in_sizes[0] == B * 6) {
        theta = (const float*)d_in[0];
        X     = (const float*)d_in[1];
    }
    float* out = (float*)d_out;

    dim3 grid(B * NBY * NBX);   // 4096 blocks (16x16 tiles)
    dim3 block(256);
    bilerp_kernel<<<grid, block>>>(X, theta, out);
}